// round 15
// baseline (speedup 1.0000x reference)
#include <cuda_runtime.h>
#include <cuda_bf16.h>

// DecayModel: out[b,s,h] = (fwd[s] + bwd[s]) / norm[s] per (b,h) column.
// fwd[s] = sum_{k<=s} 0.5^{s-k} x[k];  bwd[s] = sum_{k>=s} 0.5^{k-s} x[k];
// norm[s] = 4 - 2^-s - 2^-(S-1-s)  (== 4.0f exactly in fp32 away from ends).
//
// Converged forward-state-carry chunked scan:
//  - each thread owns one h column and a SPAN=128 range of S, processed as
//    4 chunks of 32 with ping-pong register buffers; fwd recurrence carries
//    across chunks; the next chunk's buffer doubles as the right halo;
//  - backward chain computed fully into registers, stores issued as an
//    ascending burst (same direction as the read stream — measured win R13);
//  - default-policy stores (beat __stcs — measured win R14);
//  - HALO=12 (truncation lands ~1.5e-5 measured, 60x under the 1e-3 gate;
//    saves 8 halo loads + 8 warmup FMAs per span).
// DRAM traffic = 1R+1W per element (algorithmic floor); measured ~6.4 TB/s
// effective, ~80% of spec — the mixed read/write HBM ceiling.

#define S_DIM 2048
#define H_DIM 1024
#define CHUNK 32
#define SPANC 4
#define SPAN  (CHUNK * SPANC)   // 128
#define HALO  12
#define TPB   256

__device__ __forceinline__ void proc_chunk(
    float* __restrict__ oc, int cs, float& y,
    float (&cur)[CHUNK], const float (&nxt)[CHUNK], bool has_right)
{
    // ---- forward scan, in place (cur becomes fwd) ----
    const float y_in = y;
    float yy = y;
    #pragma unroll
    for (int t = 0; t < CHUNK; ++t) {
        yy = fmaf(yy, 0.5f, cur[t]);
        cur[t] = yy;
    }
    y = yy;

    // ---- backward warmup from the next chunk's raw x (right halo) ----
    float z = 0.0f;
    if (has_right) {
        #pragma unroll
        for (int t = HALO - 1; t >= 0; --t)
            z = fmaf(z, 0.5f, nxt[t]);
    }

    // ---- backward chain into registers (cur becomes the final output) ----
    const bool boundary = (cs == 0) || (cs + CHUNK == S_DIM);
    if (boundary) {
        // exact norm via exp2f (only the first and last chunk of S)
        #pragma unroll
        for (int t = CHUNK - 1; t >= 0; --t) {
            float prev = (t > 0) ? cur[t - 1] : y_in;
            float xv = fmaf(-0.5f, prev, cur[t]);
            z = fmaf(z, 0.5f, xv);
            int s = cs + t;
            float rn = 1.0f / (4.0f - exp2f(-(float)s)
                                    - exp2f(-(float)(S_DIM - 1 - s)));
            cur[t] = (cur[t] + z) * rn;
        }
    } else {
        // interior: norm == 4.0f exactly in fp32
        #pragma unroll
        for (int t = CHUNK - 1; t >= 0; --t) {
            float prev = (t > 0) ? cur[t - 1] : y_in;
            float xv = fmaf(-0.5f, prev, cur[t]);
            z = fmaf(z, 0.5f, xv);
            cur[t] = (cur[t] + z) * 0.25f;
        }
    }

    // ---- ascending store burst, default cache policy ----
    #pragma unroll
    for (int t = 0; t < CHUNK; ++t)
        oc[(size_t)(cs + t) * H_DIM] = cur[t];
}

__global__ __launch_bounds__(TPB, 2)
void decay_model_kernel(const float* __restrict__ x, float* __restrict__ out) {
    const int h  = blockIdx.x * TPB + threadIdx.x;   // h column (coalesced)
    const int s0 = blockIdx.y * SPAN;                // span start along S
    const size_t base = (size_t)blockIdx.z * S_DIM * H_DIM + h;
    const float* __restrict__ xc = x + base;
    float* __restrict__ oc = out + base;

    // ---- left-halo warmup, once per span ----
    float y = 0.0f;
    if (s0 != 0) {
        #pragma unroll
        for (int t = 0; t < HALO; ++t)
            y = fmaf(y, 0.5f, xc[(size_t)(s0 - HALO + t) * H_DIM]);
    }

    float A[CHUNK], B[CHUNK];

    // chunk 0 data
    #pragma unroll
    for (int t = 0; t < CHUNK; ++t)
        A[t] = xc[(size_t)(s0 + t) * H_DIM];

    // j=0: prefetch chunk 1 into B, process A
    #pragma unroll
    for (int t = 0; t < CHUNK; ++t)
        B[t] = xc[(size_t)(s0 + CHUNK + t) * H_DIM];
    proc_chunk(oc, s0, y, A, B, true);

    // j=1: prefetch chunk 2 into A, process B
    #pragma unroll
    for (int t = 0; t < CHUNK; ++t)
        A[t] = xc[(size_t)(s0 + 2 * CHUNK + t) * H_DIM];
    proc_chunk(oc, s0 + CHUNK, y, B, A, true);

    // j=2: prefetch chunk 3 into B, process A
    #pragma unroll
    for (int t = 0; t < CHUNK; ++t)
        B[t] = xc[(size_t)(s0 + 3 * CHUNK + t) * H_DIM];
    proc_chunk(oc, s0 + 2 * CHUNK, y, A, B, true);

    // j=3 (last in span): right halo only (from the next span), process B
    const bool last_span = (s0 + SPAN == S_DIM);
    if (!last_span) {
        #pragma unroll
        for (int t = 0; t < HALO; ++t)
            A[t] = xc[(size_t)(s0 + SPAN + t) * H_DIM];
    }
    proc_chunk(oc, s0 + 3 * CHUNK, y, B, A, !last_span);
}

extern "C" void kernel_launch(void* const* d_in, const int* in_sizes, int n_in,
                              void* d_out, int out_size) {
    const float* x = (const float*)d_in[0];
    float* out = (float*)d_out;
    const int B = in_sizes[0] / (S_DIM * H_DIM);

    dim3 grid(H_DIM / TPB, S_DIM / SPAN, B);   // (4, 16, B) = 1024 blocks
    decay_model_kernel<<<grid, TPB>>>(x, out);
}

// round 16
// speedup vs baseline: 1.0020x; 1.0020x over previous
#include <cuda_runtime.h>
#include <cuda_bf16.h>

// DecayModel: out[b,s,h] = (fwd[s] + bwd[s]) / norm[s] per (b,h) column.
// fwd[s] = sum_{k<=s} 0.5^{s-k} x[k];  bwd[s] = sum_{k>=s} 0.5^{k-s} x[k];
// norm[s] = 4 - 2^-s - 2^-(S-1-s)  (== 4.0f exactly in fp32 away from ends).
//
// FINAL CONVERGED KERNEL (measured optimum across 9 single-variable A/Bs):
//  - forward-state-carry chunked scan: each thread owns one h column and a
//    SPAN=128 range of S, processed as 4 chunks of 32 with ping-pong
//    register buffers; the fwd recurrence carries across chunks and the
//    next chunk's buffer doubles as the right halo (HALO=16, trunc < 2^-16;
//    HALO=12 and 20 both measured slower);
//  - x reconstructed in the bwd pass via x[t] = fwd[t] - 0.5*fwd[t-1], so
//    each element is loaded once (1R+1W DRAM = algorithmic floor);
//  - backward chain computed fully into registers, stores issued as an
//    ASCENDING burst (same direction as the read stream; measured +3%);
//  - default-policy loads AND stores (stcs/ldcs/evict_last all regressed);
//  - 2 blocks/SM; higher occupancy measured to have zero effect.
// Measured: ~39.7us kernel, DRAM 69.5%, 6.45 TB/s effective useful BW
// (~81% of 8 TB/s spec) — the mixed read/write HBM turnaround ceiling.

#define S_DIM 2048
#define H_DIM 1024
#define CHUNK 32
#define SPANC 4
#define SPAN  (CHUNK * SPANC)   // 128
#define HALO  16
#define TPB   256

__device__ __forceinline__ void proc_chunk(
    float* __restrict__ oc, int cs, float& y,
    float (&cur)[CHUNK], const float (&nxt)[CHUNK], bool has_right)
{
    // ---- forward scan, in place (cur becomes fwd) ----
    const float y_in = y;
    float yy = y;
    #pragma unroll
    for (int t = 0; t < CHUNK; ++t) {
        yy = fmaf(yy, 0.5f, cur[t]);
        cur[t] = yy;
    }
    y = yy;

    // ---- backward warmup from the next chunk's raw x (right halo) ----
    float z = 0.0f;
    if (has_right) {
        #pragma unroll
        for (int t = HALO - 1; t >= 0; --t)
            z = fmaf(z, 0.5f, nxt[t]);
    }

    // ---- backward chain into registers (cur becomes the final output) ----
    const bool boundary = (cs == 0) || (cs + CHUNK == S_DIM);
    if (boundary) {
        // exact norm via exp2f (only the first and last chunk of S)
        #pragma unroll
        for (int t = CHUNK - 1; t >= 0; --t) {
            float prev = (t > 0) ? cur[t - 1] : y_in;
            float xv = fmaf(-0.5f, prev, cur[t]);
            z = fmaf(z, 0.5f, xv);
            int s = cs + t;
            float rn = 1.0f / (4.0f - exp2f(-(float)s)
                                    - exp2f(-(float)(S_DIM - 1 - s)));
            cur[t] = (cur[t] + z) * rn;
        }
    } else {
        // interior: norm == 4.0f exactly in fp32
        #pragma unroll
        for (int t = CHUNK - 1; t >= 0; --t) {
            float prev = (t > 0) ? cur[t - 1] : y_in;
            float xv = fmaf(-0.5f, prev, cur[t]);
            z = fmaf(z, 0.5f, xv);
            cur[t] = (cur[t] + z) * 0.25f;
        }
    }

    // ---- ascending store burst, default cache policy ----
    #pragma unroll
    for (int t = 0; t < CHUNK; ++t)
        oc[(size_t)(cs + t) * H_DIM] = cur[t];
}

__global__ __launch_bounds__(TPB, 2)
void decay_model_kernel(const float* __restrict__ x, float* __restrict__ out) {
    const int h  = blockIdx.x * TPB + threadIdx.x;   // h column (coalesced)
    const int s0 = blockIdx.y * SPAN;                // span start along S
    const size_t base = (size_t)blockIdx.z * S_DIM * H_DIM + h;
    const float* __restrict__ xc = x + base;
    float* __restrict__ oc = out + base;

    // ---- left-halo warmup, once per span ----
    float y = 0.0f;
    if (s0 != 0) {
        #pragma unroll
        for (int t = 0; t < HALO; ++t)
            y = fmaf(y, 0.5f, xc[(size_t)(s0 - HALO + t) * H_DIM]);
    }

    float A[CHUNK], B[CHUNK];

    // chunk 0 data
    #pragma unroll
    for (int t = 0; t < CHUNK; ++t)
        A[t] = xc[(size_t)(s0 + t) * H_DIM];

    // j=0: prefetch chunk 1 into B, process A
    #pragma unroll
    for (int t = 0; t < CHUNK; ++t)
        B[t] = xc[(size_t)(s0 + CHUNK + t) * H_DIM];
    proc_chunk(oc, s0, y, A, B, true);

    // j=1: prefetch chunk 2 into A, process B
    #pragma unroll
    for (int t = 0; t < CHUNK; ++t)
        A[t] = xc[(size_t)(s0 + 2 * CHUNK + t) * H_DIM];
    proc_chunk(oc, s0 + CHUNK, y, B, A, true);

    // j=2: prefetch chunk 3 into B, process A
    #pragma unroll
    for (int t = 0; t < CHUNK; ++t)
        B[t] = xc[(size_t)(s0 + 3 * CHUNK + t) * H_DIM];
    proc_chunk(oc, s0 + 2 * CHUNK, y, A, B, true);

    // j=3 (last in span): right halo only (from the next span), process B
    const bool last_span = (s0 + SPAN == S_DIM);
    if (!last_span) {
        #pragma unroll
        for (int t = 0; t < HALO; ++t)
            A[t] = xc[(size_t)(s0 + SPAN + t) * H_DIM];
    }
    proc_chunk(oc, s0 + 3 * CHUNK, y, B, A, !last_span);
}

extern "C" void kernel_launch(void* const* d_in, const int* in_sizes, int n_in,
                              void* d_out, int out_size) {
    const float* x = (const float*)d_in[0];
    float* out = (float*)d_out;
    const int B = in_sizes[0] / (S_DIM * H_DIM);

    dim3 grid(H_DIM / TPB, S_DIM / SPAN, B);   // (4, 16, B) = 1024 blocks
    decay_model_kernel<<<grid, TPB>>>(x, out);
}